// round 17
// baseline (speedup 1.0000x reference)
#include <cuda_runtime.h>
#include <cuda_fp16.h>
#include <cstdint>
#include <math.h>

// Problem dims (fixed by reference setup_inputs)
#define BB 4
#define TT 4096
#define HH 1024
#define M_TOTAL (BB*TT)      // 16384
#define NCHUNK 128
#define CHUNK (TT/NCHUNK)    // 32
#define NCTA (BB*NCHUNK)     // 512 scan CTAs

// Scratch (allocation-free rule: __device__ globals)
__device__ __half g_normh[(size_t)M_TOTAL*HH];   // fp16 LN output (32MB)
__device__ __half g_Wh[(size_t)2*HH*HH];         // fp16 [Wg; Wc] (4MB)
__device__ __half g_zh[(size_t)M_TOTAL*HH];      // fp16 gate (32MB)
__device__ __half g_ch[(size_t)M_TOTAL*HH];      // fp16 candidate (32MB)
// Decoupled-lookback scan state:
__device__ float4 g_agg[(size_t)NCTA*(HH/2)];    // chunk aggregate (Px,Py,Sx,Sy) (4MB)
__device__ float2 g_inc[(size_t)NCTA*(HH/2)];    // chunk inclusive prefix value (2MB)
__device__ int    g_flag[NCTA];                  // 0=none, 1=agg ready, 2=inclusive ready

__device__ __forceinline__ uint32_t smem_u32(const void* p) {
    uint32_t a;
    asm("{ .reg .u64 t; cvta.to.shared.u64 t, %1; cvt.u32.u64 %0, t; }" : "=r"(a) : "l"(p));
    return a;
}
__device__ __forceinline__ void cp16(uint32_t dst, const void* src) {
    asm volatile("cp.async.cg.shared.global [%0], [%1], 16;" :: "r"(dst), "l"(src));
}

// ---------------------------------------------------------------------------
// Kernel 1: fused LayerNorm + weight conversion + scan-flag clear (role-split).
// Blocks [0, LN_BLOCKS): LN warp-per-row -> fp16 normed.
// Blocks [LN_BLOCKS, +HW_BLOCKS): convert Wg/Wc -> g_Wh.
// Blocks [LN_BLOCKS+HW_BLOCKS, +2): clear g_flag (fresh sync state per call).
// ---------------------------------------------------------------------------
#define LN_BLOCKS (M_TOTAL / 8)              // 2048
#define HW_BLOCKS ((2 * HH * HH / 4) / 256)  // 2048
#define FC_BLOCKS (NCTA / 256)               // 2

__global__ __launch_bounds__(256) void ln_halfw_kernel(
    const float* __restrict__ x,
    const float* __restrict__ gamma,
    const float* __restrict__ beta,
    const float* __restrict__ Wg,
    const float* __restrict__ Wc) {
    if (blockIdx.x >= LN_BLOCKS + HW_BLOCKS) {
        // ---- flag-clear role ----
        int i = (blockIdx.x - LN_BLOCKS - HW_BLOCKS) * blockDim.x + threadIdx.x;
        g_flag[i] = 0;
        return;
    }
    if (blockIdx.x >= LN_BLOCKS) {
        // ---- weight-conversion role ----
        int i = (blockIdx.x - LN_BLOCKS) * blockDim.x + threadIdx.x;
        int half_n = HH * HH / 4;
        const float4* src = (i < half_n) ? (const float4*)Wg : (const float4*)Wc;
        float4 v = src[(i < half_n) ? i : (i - half_n)];
        __half2 h0 = __floats2half2_rn(v.x, v.y);
        __half2 h1 = __floats2half2_rn(v.z, v.w);
        ((uint2*)g_Wh)[i] = make_uint2(*(uint32_t*)&h0, *(uint32_t*)&h1);
        return;
    }
    // ---- LayerNorm role: warp-per-row, pure shfl reduction ----
    int warp = threadIdx.x >> 5, lane = threadIdx.x & 31;
    int row = blockIdx.x * 8 + warp;
    const float4* xr = (const float4*)(x + (size_t)row * HH);

    float4 v[8];
    float s = 0.f, s2 = 0.f;
    #pragma unroll
    for (int q = 0; q < 8; q++) {
        v[q] = xr[lane + 32 * q];
        s  += v[q].x + v[q].y + v[q].z + v[q].w;
        s2 += v[q].x*v[q].x + v[q].y*v[q].y + v[q].z*v[q].z + v[q].w*v[q].w;
    }
    #pragma unroll
    for (int o = 16; o > 0; o >>= 1) {
        s  += __shfl_xor_sync(0xFFFFFFFFu, s,  o);
        s2 += __shfl_xor_sync(0xFFFFFFFFu, s2, o);
    }
    float mu  = s * (1.f / HH);
    float var = s2 * (1.f / HH) - mu * mu;
    float rs  = rsqrtf(var + 1e-5f);

    uint2* orow = (uint2*)g_normh + (size_t)row * (HH / 4);
    #pragma unroll
    for (int q = 0; q < 8; q++) {
        int f = lane + 32 * q;
        float4 g  = ((const float4*)gamma)[f];
        float4 bt = ((const float4*)beta)[f];
        __half2 h0 = __floats2half2_rn((v[q].x - mu) * rs * g.x + bt.x,
                                       (v[q].y - mu) * rs * g.y + bt.y);
        __half2 h1 = __floats2half2_rn((v[q].z - mu) * rs * g.z + bt.z,
                                       (v[q].w - mu) * rs * g.w + bt.w);
        orow[f] = make_uint2(*(uint32_t*)&h0, *(uint32_t*)&h1);
    }
}

// ---------------------------------------------------------------------------
// Kernel 2: fp16 mma.sync (m16n8k16) GEMM, cp.async 4-stage pipeline,
// ldmatrix fragment loads. Block tile 128x128, BK=32, 4 warps (128 thr),
// warp tile 64x64 (2x2 warp grid). 2 CTAs/SM. At the mma.sync HMMA ceiling.
// Logical N = 2048: bn<8 -> Wg+sigmoid -> g_zh, bn>=8 -> g_ch.
// ---------------------------------------------------------------------------
#define BM 128
#define BN 128
#define BK 32                            // halves per K-tile
#define STAGES 4
#define SSTR_H 40                        // halves per smem row (80B: ldmatrix conflict-free)
#define A_STAGE_H (BM*SSTR_H)            // 5120 halves
#define B_STAGE_H (BN*SSTR_H)
#define GEMM_SMEM (STAGES*(A_STAGE_H+B_STAGE_H)*2)   // 81920 B

__global__ __launch_bounds__(128, 2) void gemm_kernel(
    const float* __restrict__ bg, const float* __restrict__ bc)
{
    extern __shared__ __half smh[];
    uint32_t sA_u = smem_u32(smh);
    uint32_t sB_u = sA_u + STAGES * A_STAGE_H * 2;

    int tid = threadIdx.x;               // 128
    int warp = tid >> 5, lane = tid & 31;
    int bn = blockIdx.x;                 // 0..15 (fast -> wave shares A in L2)
    int bm = blockIdx.y;                 // 0..127
    int wm = (warp & 1) * 64;            // 2 M-warps
    int wn = (warp >> 1) * 64;           // 2 N-warps

    bool isGate = (bn < 8);
    size_t woff = isGate ? 0 : (size_t)HH * HH;
    int nbase = (bn & 7) * BN;
    size_t arow = (size_t)bm * BM;

    const __half* Asrc0 = g_normh + arow * HH;
    const __half* Bsrc0 = g_Wh + woff + (size_t)nbase * HH;

    float acc[4][8][4];                  // 4 m16 x 8 n8 x 4 regs
    #pragma unroll
    for (int i = 0; i < 4; i++)
        #pragma unroll
        for (int j = 0; j < 8; j++)
            #pragma unroll
            for (int q = 0; q < 4; q++) acc[i][j][q] = 0.f;

    // loads: per stage A 512 + B 512 16B-chunks, 128 thr -> 4+4 each
    int lr[4], lc[4];
    #pragma unroll
    for (int q = 0; q < 4; q++) {
        int f = tid + q * 128;
        lr[q] = f >> 2;                  // row 0..127
        lc[q] = (f & 3) * 8;             // half offset in row (16B chunks)
    }

    #define LOAD_STAGE(s, k0) do { \
        uint32_t abase = sA_u + (uint32_t)(s) * A_STAGE_H * 2; \
        uint32_t bbase = sB_u + (uint32_t)(s) * B_STAGE_H * 2; \
        _Pragma("unroll") \
        for (int q = 0; q < 4; q++) { \
            cp16(abase + (uint32_t)(lr[q] * SSTR_H + lc[q]) * 2, \
                 Asrc0 + (size_t)lr[q] * HH + (k0) + lc[q]); \
            cp16(bbase + (uint32_t)(lr[q] * SSTR_H + lc[q]) * 2, \
                 Bsrc0 + (size_t)lr[q] * HH + (k0) + lc[q]); \
        } \
    } while (0)

    LOAD_STAGE(0, 0);
    asm volatile("cp.async.commit_group;");
    LOAD_STAGE(1, BK);
    asm volatile("cp.async.commit_group;");
    LOAD_STAGE(2, 2 * BK);
    asm volatile("cp.async.commit_group;");

    // per-lane ldmatrix address components (bytes)
    uint32_t a_row = (uint32_t)(lane & 15);          // row within m16
    uint32_t a_kb  = ((lane >> 4) & 1) * 16;         // +8 halves
    uint32_t b_row = (uint32_t)((lane & 7) + ((lane >> 4) & 1) * 8);  // row within n16
    uint32_t b_kb  = ((lane >> 3) & 1) * 16;

    const int NK = HH / BK;              // 32
    for (int i = 0; i < NK; i++) {
        int s = i & (STAGES - 1);
        asm volatile("cp.async.wait_group 2;");
        __syncthreads();
        if (i + 3 < NK) {
            int s2 = (i + 3) & (STAGES - 1);
            LOAD_STAGE(s2, (i + 3) * BK);
        }
        asm volatile("cp.async.commit_group;");

        uint32_t abase = sA_u + (uint32_t)s * A_STAGE_H * 2;
        uint32_t bbase = sB_u + (uint32_t)s * B_STAGE_H * 2;

        #pragma unroll
        for (int ks = 0; ks < 2; ks++) {     // two k16 steps per K-tile
            unsigned af[4][4];
            #pragma unroll
            for (int ii = 0; ii < 4; ii++) {
                uint32_t addr = abase + (wm + ii * 16 + a_row) * (SSTR_H * 2)
                                + ks * 32 + a_kb;
                asm volatile(
                    "ldmatrix.sync.aligned.m8n8.x4.shared.b16 {%0,%1,%2,%3}, [%4];"
                    : "=r"(af[ii][0]), "=r"(af[ii][1]), "=r"(af[ii][2]), "=r"(af[ii][3])
                    : "r"(addr));
            }
            unsigned bf[8][2];
            #pragma unroll
            for (int j2 = 0; j2 < 4; j2++) {  // each x4 covers two n8 subtiles
                uint32_t addr = bbase + (wn + j2 * 16 + b_row) * (SSTR_H * 2)
                                + ks * 32 + b_kb;
                asm volatile(
                    "ldmatrix.sync.aligned.m8n8.x4.shared.b16 {%0,%1,%2,%3}, [%4];"
                    : "=r"(bf[j2*2][0]), "=r"(bf[j2*2][1]),
                      "=r"(bf[j2*2+1][0]), "=r"(bf[j2*2+1][1])
                    : "r"(addr));
            }
            #pragma unroll
            for (int ii = 0; ii < 4; ii++) {
                #pragma unroll
                for (int j = 0; j < 8; j++) {
                    float* a4 = acc[ii][j];
                    asm volatile(
                        "mma.sync.aligned.m16n8k16.row.col.f32.f16.f16.f32 "
                        "{%0,%1,%2,%3},{%4,%5,%6,%7},{%8,%9},{%0,%1,%2,%3};"
                        : "+f"(a4[0]), "+f"(a4[1]), "+f"(a4[2]), "+f"(a4[3])
                        : "r"(af[ii][0]), "r"(af[ii][1]), "r"(af[ii][2]), "r"(af[ii][3]),
                          "r"(bf[j][0]), "r"(bf[j][1]));
                }
            }
        }
    }
    asm volatile("cp.async.wait_group 0;");

    // Epilogue: +bias, optional sigmoid, write z or c as fp16
    int r  = lane >> 2;
    int cq = (lane & 3) * 2;
    const float* bias = isGate ? bg : bc;
    __half* outp = isGate ? g_zh : g_ch;
    #pragma unroll
    for (int ii = 0; ii < 4; ii++) {
        #pragma unroll
        for (int j = 0; j < 8; j++) {
            float* a4 = acc[ii][j];
            int m0 = bm * BM + wm + ii * 16 + r;
            int n0 = nbase + wn + j * 8 + cq;
            float b0 = bias[n0], b1 = bias[n0 + 1];
            float v0 = a4[0] + b0;
            float v1 = a4[1] + b1;
            float v2 = a4[2] + b0;
            float v3 = a4[3] + b1;
            if (isGate) {
                v0 = 1.f / (1.f + __expf(-v0));
                v1 = 1.f / (1.f + __expf(-v1));
                v2 = 1.f / (1.f + __expf(-v2));
                v3 = 1.f / (1.f + __expf(-v3));
            }
            *(__half2*)(outp + (size_t)m0 * HH + n0)       = __floats2half2_rn(v0, v1);
            *(__half2*)(outp + (size_t)(m0 + 8) * HH + n0) = __floats2half2_rn(v2, v3);
        }
    }
}

// ---------------------------------------------------------------------------
// Kernel 3: single-pass fused scan with decoupled lookback.
// CTA = (b, ck): 256 threads, each owns hid-pairs tid and tid+256.
// Phase 1: chunk-local (P,S).  Publish aggregate (flag=1; ck=0: inclusive,
// flag=2).  Lookback over predecessors (compose aggregates until an
// inclusive).  Publish inclusive (flag=2).  Phase 2: re-run chunk (z/c now
// L2-hot) with correct h_in, fuse residual +x, write out.
// Dependencies point only to lower block ids -> safe under in-order dispatch.
// ---------------------------------------------------------------------------
__global__ __launch_bounds__(256, 4) void scan_fused_kernel(
    const float* __restrict__ x, float* __restrict__ out)
{
    int bid = blockIdx.x;                 // b*NCHUNK + ck
    int ck  = bid & (NCHUNK - 1);
    int b   = bid >> 7;                   // NCHUNK = 128
    int tid = threadIdx.x;
    int hpA = tid, hpB = tid + 256;
    size_t rowbase = ((size_t)(b * TT + ck * CHUNK)) * HH;

    // --- Phase 1: chunk-local scan (4 independent FFMA chains) ---
    float2 P[2] = {make_float2(1.f, 1.f), make_float2(1.f, 1.f)};
    float2 S[2] = {make_float2(0.f, 0.f), make_float2(0.f, 0.f)};
    #pragma unroll 4
    for (int t = 0; t < CHUNK; t++) {
        size_t r = rowbase + (size_t)t * HH;
        #pragma unroll
        for (int u = 0; u < 2; u++) {
            int hp = u ? hpB : hpA;
            float2 z = __half22float2(*(const __half2*)(g_zh + r + 2 * hp));
            float2 c = __half22float2(*(const __half2*)(g_ch + r + 2 * hp));
            float ax = 1.f - z.x, ay = 1.f - z.y;
            S[u].x = ax * S[u].x + z.x * c.x;  P[u].x *= ax;
            S[u].y = ay * S[u].y + z.y * c.y;  P[u].y *= ay;
        }
    }

    size_t abase = (size_t)bid * (HH / 2);
    if (ck == 0) {
        g_inc[abase + hpA] = S[0];
        g_inc[abase + hpB] = S[1];
    } else {
        g_agg[abase + hpA] = make_float4(P[0].x, P[0].y, S[0].x, S[0].y);
        g_agg[abase + hpB] = make_float4(P[1].x, P[1].y, S[1].x, S[1].y);
    }
    __threadfence();
    __syncthreads();
    if (tid == 0)
        *(volatile int*)&g_flag[bid] = (ck == 0) ? 2 : 1;

    // --- Lookback: exclusive prefix value per hid ---
    float2 ex[2] = {make_float2(0.f, 0.f), make_float2(0.f, 0.f)};
    if (ck > 0) {
        float2 rP[2] = {make_float2(1.f, 1.f), make_float2(1.f, 1.f)};
        float2 rS[2] = {make_float2(0.f, 0.f), make_float2(0.f, 0.f)};
        int j = bid - 1;
        while (true) {
            int f;
            do { f = *(volatile int*)&g_flag[j]; } while (f == 0);
            __threadfence();
            size_t jb = (size_t)j * (HH / 2);
            if (f == 2) {
                #pragma unroll
                for (int u = 0; u < 2; u++) {
                    int hp = u ? hpB : hpA;
                    float2 inc = g_inc[jb + hp];
                    ex[u].x = rP[u].x * inc.x + rS[u].x;
                    ex[u].y = rP[u].y * inc.y + rS[u].y;
                }
                break;
            }
            #pragma unroll
            for (int u = 0; u < 2; u++) {
                int hp = u ? hpB : hpA;
                float4 A = g_agg[jb + hp];
                rS[u].x = rP[u].x * A.z + rS[u].x;  rP[u].x *= A.x;
                rS[u].y = rP[u].y * A.w + rS[u].y;  rP[u].y *= A.y;
            }
            j--;
        }
        // publish own inclusive
        #pragma unroll
        for (int u = 0; u < 2; u++) {
            int hp = u ? hpB : hpA;
            float2 inc;
            inc.x = P[u].x * ex[u].x + S[u].x;
            inc.y = P[u].y * ex[u].y + S[u].y;
            g_inc[abase + hp] = inc;
        }
        __threadfence();
        __syncthreads();
        if (tid == 0) *(volatile int*)&g_flag[bid] = 2;
    }

    // --- Phase 2: re-run chunk with h_in, fuse residual, write out ---
    float2 h[2] = {ex[0], ex[1]};
    #pragma unroll 4
    for (int t = 0; t < CHUNK; t++) {
        size_t r = rowbase + (size_t)t * HH;
        #pragma unroll
        for (int u = 0; u < 2; u++) {
            int hp = u ? hpB : hpA;
            float2 z = __half22float2(*(const __half2*)(g_zh + r + 2 * hp));
            float2 c = __half22float2(*(const __half2*)(g_ch + r + 2 * hp));
            h[u].x = (1.f - z.x) * h[u].x + z.x * c.x;
            h[u].y = (1.f - z.y) * h[u].y + z.y * c.y;
            float2 xv = *(const float2*)(x + r + 2 * hp);
            *(float2*)(out + r + 2 * hp) = make_float2(h[u].x + xv.x, h[u].y + xv.y);
        }
    }
}

// ---------------------------------------------------------------------------
extern "C" void kernel_launch(void* const* d_in, const int* in_sizes, int n_in,
                              void* d_out, int out_size) {
    const float* x     = (const float*)d_in[0];
    const float* gamma = (const float*)d_in[1];
    const float* beta  = (const float*)d_in[2];
    const float* Wg    = (const float*)d_in[3];
    const float* bg    = (const float*)d_in[4];
    const float* Wc    = (const float*)d_in[5];
    const float* bc    = (const float*)d_in[6];
    float* out = (float*)d_out;

    ln_halfw_kernel<<<LN_BLOCKS + HW_BLOCKS + FC_BLOCKS, 256>>>(x, gamma, beta, Wg, Wc);

    cudaFuncSetAttribute(gemm_kernel,
                         cudaFuncAttributeMaxDynamicSharedMemorySize, GEMM_SMEM);
    dim3 ggrid(2 * HH / BN, M_TOTAL / BM);   // (16, 128)
    gemm_kernel<<<ggrid, 128, GEMM_SMEM>>>(bg, bc);

    scan_fused_kernel<<<NCTA, 256>>>(x, out);
}